// round 7
// baseline (speedup 1.0000x reference)
#include <cuda_runtime.h>
#include <cstdint>

#define N_PTS   131072
#define C_DIM   64
#define K_CB    512
#define NQ      4
#define HW_SZ   16384
#define P_BLK   32
#define NTHR    256
#define KPT     8          // k's per thread
#define PPT     8          // points per thread tile
#define NBLK    (N_PTS / P_BLK)
#define WLCAP   512
#define IDX_OFF 8388608
#define LOSS_OFF 8912896

// Scratch (allocation-free rule: __device__ globals)
__device__ float    g_G[K_CB * K_CB];  // Gram matrix cb @ cb.T (fast path only)
__device__ float    g_h[K_CB];         // 0.5 * ||cb_k||^2      (fast path only)
__device__ float    g_csq[K_CB];       // ||cb_k||^2, XLA-CPU vectorized-reduce order
__device__ float    g_cbT[C_DIM * K_CB]; // transposed codebook [c][k] for cp.async
__device__ double   g_loss[NQ];        // double loss accumulators
__device__ unsigned g_done = 0;        // last-block counter

__device__ __forceinline__ void cpasync16(uint32_t dst, const float* src) {
    asm volatile("cp.async.ca.shared.global [%0], [%1], 16;\n"
                 :: "r"(dst), "l"(src));
}
#define CP_COMMIT() asm volatile("cp.async.commit_group;\n" ::)
#define CP_WAIT0()  asm volatile("cp.async.wait_group 0;\n" ::)

// ---------------------------------------------------------------------------
// Precompute G, h, csq, cbT; zero loss accumulators.
// ---------------------------------------------------------------------------
__global__ void prep_kernel(const float* __restrict__ cb) {
    __shared__ float ci[C_DIM];
    const int i = blockIdx.x;
    const int t = threadIdx.x;
    if (t < C_DIM) ci[t] = cb[i * C_DIM + t];
    __syncthreads();
    {
        const float4* row = (const float4*)(cb + t * C_DIM);
        float s = 0.f;
#pragma unroll
        for (int c4 = 0; c4 < 16; c4++) {
            float4 v = row[c4];
            s = fmaf(ci[4 * c4 + 0], v.x, s);
            s = fmaf(ci[4 * c4 + 1], v.y, s);
            s = fmaf(ci[4 * c4 + 2], v.z, s);
            s = fmaf(ci[4 * c4 + 3], v.w, s);
        }
        g_G[i * K_CB + t] = s;
        if (t == i) g_h[i] = 0.5f * s;
    }
    if (t < C_DIM) g_cbT[t * K_CB + i] = ci[t];   // transposed copy
    if (t == 0) {
        // csq exactly as XLA:CPU vectorized reduce (NEON width 4):
        // 4 strided lane accumulators, strict per-op rounding (mul+add,
        // no FMA), shuffle-halving horizontal sum: (L0+L2)+(L1+L3).
        float l0 = 0.f, l1 = 0.f, l2 = 0.f, l3 = 0.f;
        for (int j = 0; j < 16; j++) {
            float v0 = ci[4 * j + 0], v1 = ci[4 * j + 1];
            float v2 = ci[4 * j + 2], v3 = ci[4 * j + 3];
            l0 = __fadd_rn(l0, __fmul_rn(v0, v0));
            l1 = __fadd_rn(l1, __fmul_rn(v1, v1));
            l2 = __fadd_rn(l2, __fmul_rn(v2, v2));
            l3 = __fadd_rn(l3, __fmul_rn(v3, v3));
        }
        g_csq[i] = __fadd_rn(__fadd_rn(l0, l2), __fadd_rn(l1, l3));
    }
    if (i == 0 && t < NQ) g_loss[t] = 0.0;
}

// Orderable-float packing: larger float -> larger uint (monotone).
__device__ __forceinline__ unsigned ford(float f) {
    unsigned u = __float_as_uint(f);
    return (u & 0x80000000u) ? ~u : (u | 0x80000000u);
}
__device__ __forceinline__ float funord(unsigned s) {
    unsigned u = (s & 0x80000000u) ? (s ^ 0x80000000u) : ~s;
    return __uint_as_float(u);
}

// ---------------------------------------------------------------------------
// Main fused RVQ kernel. Block = 32 points x 512 codewords, 256 threads,
// 2 blocks/SM. Thread tile: 8 points (pg = tid&3) x 8 k's (kg = tid>>2).
// acc[8][8] = 64 regs at the 128-reg cap (no spill). Codebook chunks are
// double-buffered via cp.async from the pre-transposed g_cbT.
// ---------------------------------------------------------------------------
__global__ __launch_bounds__(NTHR, 2)
void rvq_kernel(const float* __restrict__ x, const float* __restrict__ cb,
                float* __restrict__ out) {
    __shared__ float rs[C_DIM][P_BLK];          // exact residual, [c][p]  8KB
    __shared__ float cbs[2][8][K_CB];           // double-buffered chunk   32KB
    __shared__ unsigned red1[P_BLK];            // fast max per point
    __shared__ unsigned long long redmin[P_BLK];// packed (dist,k) argmin
    __shared__ int    idxs[NQ][P_BLK];
    __shared__ double sloss[NQ];
    __shared__ int    wl[WLCAP];                // candidate worklist (p<<9|k)
    __shared__ int    wl_n;

    const int tid   = threadIdx.x;
    const int lane  = tid & 31;
    const int pg    = tid & 3;                  // 0..3, 8 points each
    const int kg    = tid >> 2;                 // 0..63
    const int kbase = kg * KPT;
    const int n0    = blockIdx.x * P_BLK;
    const int b     = n0 / HW_SZ;               // 32 | HW, block never crosses b
    const int hw0   = n0 % HW_SZ;
    const float* xbase = x + (size_t)b * C_DIM * HW_SZ + hw0;

    if (tid < P_BLK) { red1[tid] = 0u; redmin[tid] = ~0ull; }
    if (tid < NQ)    sloss[tid] = 0.0;
    if (tid == 0)    wl_n = 0;

    const int p_e  = tid & 31;       // elementwise-phase point (== lane)
    const int cg_e = tid >> 5;       // elementwise-phase channel group (0..7)

    // ---- load x tile (coalesced over p); rs starts as x (exact residual) ----
#pragma unroll
    for (int ii = 0; ii < 8; ii++) {
        const int c = cg_e * 8 + ii;
        rs[c][p_e] = xbase[(size_t)c * HW_SZ + p_e];
    }

    // ---- fast scores: acc[k] = x.c - 0.5||c||^2 (candidate filter only) ----
    float acc[PPT][KPT];
    {
        float4 h0 = *((const float4*)(g_h + kbase));
        float4 h1 = *((const float4*)(g_h + kbase + 4));
#pragma unroll
        for (int i = 0; i < PPT; i++) {
            acc[i][0] = -h0.x; acc[i][1] = -h0.y;
            acc[i][2] = -h0.z; acc[i][3] = -h0.w;
            acc[i][4] = -h1.x; acc[i][5] = -h1.y;
            acc[i][6] = -h1.z; acc[i][7] = -h1.w;
        }
    }

    const uint32_t cbs_base = (uint32_t)__cvta_generic_to_shared(&cbs[0][0][0]);
    // prologue: stream chunk 0 (channels 0..7, all 512 k) into buffer 0
    {
#pragma unroll
        for (int it = 0; it < 4; it++) {
            const int o16 = tid + it * NTHR;           // 0..1023 16B-chunks
            cpasync16(cbs_base + o16 * 16, g_cbT + o16 * 4);
        }
        CP_COMMIT(); CP_WAIT0();
    }
    __syncthreads();

    for (int ct = 0; ct < 8; ct++) {
        const int buf = ct & 1;
        if (ct < 7) {   // stream next chunk into other buffer (no regs used)
            const float* src = g_cbT + (ct + 1) * 8 * K_CB;
            const uint32_t dst = cbs_base + ((ct + 1) & 1) * (8 * K_CB * 4);
#pragma unroll
            for (int it = 0; it < 4; it++) {
                const int o16 = tid + it * NTHR;
                cpasync16(dst + o16 * 16, src + o16 * 4);
            }
            CP_COMMIT();
        }
#pragma unroll
        for (int cc = 0; cc < 8; cc++) {
            const int c = ct * 8 + cc;
            float xa[PPT];
            ((float4*)xa)[0] = *((const float4*)&rs[c][pg * 8]);
            ((float4*)xa)[1] = *((const float4*)&rs[c][pg * 8 + 4]);
            float cv[KPT];
            ((float4*)cv)[0] = *((const float4*)&cbs[buf][cc][kbase]);
            ((float4*)cv)[1] = *((const float4*)&cbs[buf][cc][kbase + 4]);
#pragma unroll
            for (int i = 0; i < PPT; i++)
#pragma unroll
                for (int j = 0; j < KPT; j++)
                    acc[i][j] = fmaf(xa[i], cv[j], acc[i][j]);
        }
        if (ct < 7) { CP_WAIT0(); __syncthreads(); }
    }
    __syncthreads();

    float qsum[8];                   // quantized accumulator (8 channels of p_e)
#pragma unroll
    for (int ii = 0; ii < 8; ii++) qsum[ii] = 0.f;

    // ---- 4 quantizer stages ----
#pragma unroll
    for (int q = 0; q < NQ; q++) {
        // A: fast local max per point; shfl pre-reduce over kg (same-pg lanes
        //    differ in lane bits 2..4), then one smem atomic per (warp,point).
#pragma unroll
        for (int i = 0; i < PPT; i++) {
            float bv = acc[i][0];
#pragma unroll
            for (int j = 1; j < KPT; j++) bv = fmaxf(bv, acc[i][j]);
            bv = fmaxf(bv, __shfl_xor_sync(0xffffffffu, bv, 4));
            bv = fmaxf(bv, __shfl_xor_sync(0xffffffffu, bv, 8));
            bv = fmaxf(bv, __shfl_xor_sync(0xffffffffu, bv, 16));
            if (lane < 4) atomicMax(&red1[pg * 8 + i], ford(bv));
        }
        __syncthreads();

        // B1: scan tile, push windowed candidates to worklist
#pragma unroll
        for (int i = 0; i < PPT; i++) {
            const int p = pg * 8 + i;
            const float thr = funord(red1[p]) - 0.01f;
#pragma unroll
            for (int j = 0; j < KPT; j++) {
                if (acc[i][j] >= thr) {
                    int pos = atomicAdd(&wl_n, 1);
                    if (pos < WLCAP) wl[pos] = (p << 9) | (kbase + j);
                }
            }
        }
        __syncthreads();

        // B2: exact (reference-order) dist per candidate, one thread each
        {
            const int wn = (wl_n < WLCAP) ? wl_n : WLCAP;
            for (int t = tid; t < wn; t += NTHR) {
                const int e = wl[t];
                const int p = e >> 9;
                const int k = e & 511;
                const float4* c4 = (const float4*)(cb + k * C_DIM);
                float dot = 0.f;
#pragma unroll 4
                for (int g = 0; g < 16; g++) {           // ascending-c seq FMA
                    float4 v = c4[g];                     // (Eigen gebp order)
                    dot = fmaf(rs[4 * g + 0][p], v.x, dot);
                    dot = fmaf(rs[4 * g + 1][p], v.y, dot);
                    dot = fmaf(rs[4 * g + 2][p], v.z, dot);
                    dot = fmaf(rs[4 * g + 3][p], v.w, dot);
                }
                float dist = __fsub_rn(g_csq[k], __fmul_rn(2.0f, dot));
                unsigned long long pk =
                    ((unsigned long long)ford(dist) << 32) | (unsigned)k;
                atomicMin(&redmin[p], pk);               // min dist, then min k
            }
        }
        __syncthreads();

        // C: finalize pick, reset reducers + worklist
        if (tid < P_BLK) {
            idxs[q][tid] = (int)(unsigned)(redmin[tid] & 0xffffffffull);
            red1[tid]   = 0u;
            redmin[tid] = ~0ull;
        }
        if (tid == 0) wl_n = 0;
        __syncthreads();

        // D: exact elementwise update (replicates reference rounding chain)
        {
            const int k = idxs[q][p_e];
            const float* crow = cb + k * C_DIM + cg_e * 8;
            double ls = 0.0;
#pragma unroll
            for (int ii = 0; ii < 8; ii++) {
                const int c = cg_e * 8 + ii;
                const float cv = crow[ii];
                const float r  = rs[c][p_e];
                const float d  = __fsub_rn(cv, r);          // quant - residual
                const float qst = __fadd_rn(r, d);          // straight-through
                qsum[ii] = __fadd_rn(qsum[ii], qst);        // quant_out += qst
                rs[c][p_e] = __fsub_rn(r, cv);              // residual -= quant
                const float sq = __fmul_rn(d, d);
                ls += (double)sq;
            }
            // warp-reduce the double, single smem atomic per warp
#pragma unroll
            for (int o = 16; o; o >>= 1)
                ls += __shfl_xor_sync(0xffffffffu, ls, o);
            if (lane == 0) atomicAdd(&sloss[q], ls);
        }

        // E: fast-score cascade for next stage: acc -= G[idx] row slice
        if (q < NQ - 1) {
#pragma unroll
            for (int i = 0; i < PPT; i++) {
                const int row = idxs[q][pg * 8 + i];
                const float4* gr = (const float4*)(g_G + row * K_CB + kbase);
                float4 g0 = gr[0], g1 = gr[1];
                acc[i][0] -= g0.x; acc[i][1] -= g0.y;
                acc[i][2] -= g0.z; acc[i][3] -= g0.w;
                acc[i][4] -= g1.x; acc[i][5] -= g1.y;
                acc[i][6] -= g1.z; acc[i][7] -= g1.w;
            }
        }
        __syncthreads();
    }

    // ---- outputs ----
    // indices as float, coalesced: 128 threads cover 32 points x 4 stages
    if (tid < P_BLK * NQ) {
        const int q = tid & 3, p = tid >> 2;
        out[IDX_OFF + (size_t)(n0 + p) * NQ + q] = (float)idxs[q][p];
    }
    // quantized in [B,C,H,W] layout (coalesced over p)
    {
        float* obase = out + (size_t)b * C_DIM * HW_SZ + hw0 + p_e;
#pragma unroll
        for (int ii = 0; ii < 8; ii++) {
            const int c = cg_e * 8 + ii;
            obase[(size_t)c * HW_SZ] = qsum[ii];
        }
    }
    // commit losses: 4 global atomics per block, last block writes output
    if (tid < NQ) atomicAdd(&g_loss[tid], sloss[tid]);
    __syncthreads();
    if (tid == 0) {
        __threadfence();
        unsigned t = atomicAdd(&g_done, 1u);
        if (t == (unsigned)(gridDim.x - 1)) {
            __threadfence();
            g_done = 0;                        // reset for next launch/replay
#pragma unroll
            for (int qq = 0; qq < NQ; qq++)
                out[LOSS_OFF + qq] =
                    (float)(g_loss[qq] * (1.0 / (131072.0 * 64.0)));
        }
    }
}

extern "C" void kernel_launch(void* const* d_in, const int* in_sizes, int n_in,
                              void* d_out, int out_size) {
    (void)in_sizes; (void)n_in; (void)out_size;
    const float* x  = (const float*)d_in[0];
    const float* cb = (const float*)d_in[1];
    float* out = (float*)d_out;

    prep_kernel<<<K_CB, 512>>>(cb);
    rvq_kernel<<<NBLK, NTHR>>>(x, cb, out);
}

// round 8
// speedup vs baseline: 1.2560x; 1.2560x over previous
#include <cuda_runtime.h>
#include <cstdint>

#define N_PTS   131072
#define C_DIM   64
#define K_CB    512
#define NQ      4
#define HW_SZ   16384
#define P_BLK   16
#define NTHR    256
#define NBLK    (N_PTS / P_BLK)
#define WLCAP   512
#define IDX_OFF 8388608
#define LOSS_OFF 8912896

typedef unsigned long long ull;

// Scratch (allocation-free rule: __device__ globals)
__device__ float    g_G[K_CB * K_CB];    // NEGATED Gram -cb@cb.T (fast path)
__device__ float    g_h[K_CB];           // NEGATED half-norms -0.5||c||^2
__device__ float    g_csq[K_CB];         // ||c||^2, XLA-CPU vectorized-reduce order
__device__ float    g_cbT[C_DIM * K_CB]; // transposed codebook [c][k]
__device__ double   g_loss[NQ];
__device__ unsigned g_done = 0;

// Packed fp32x2 ops (sm_10x). Per-lane rn rounding == scalar fmaf/fadd.
__device__ __forceinline__ ull fma2(ull a, ull b, ull c) {
    ull d;
    asm("fma.rn.f32x2 %0, %1, %2, %3;" : "=l"(d) : "l"(a), "l"(b), "l"(c));
    return d;
}
__device__ __forceinline__ ull add2(ull a, ull b) {
    ull d;
    asm("add.rn.f32x2 %0, %1, %2;" : "=l"(d) : "l"(a), "l"(b));
    return d;
}
__device__ __forceinline__ ull pack2(float lo, float hi) {
    ull d;
    asm("mov.b64 %0, {%1, %2};" : "=l"(d) : "f"(lo), "f"(hi));
    return d;
}
__device__ __forceinline__ void unpack2(float& lo, float& hi, ull v) {
    asm("mov.b64 {%0, %1}, %2;" : "=f"(lo), "=f"(hi) : "l"(v));
}

// ---------------------------------------------------------------------------
// Precompute (negated) G, (negated) h, csq, cbT; zero loss accumulators.
// ---------------------------------------------------------------------------
__global__ void prep_kernel(const float* __restrict__ cb) {
    __shared__ float ci[C_DIM];
    const int i = blockIdx.x;
    const int t = threadIdx.x;
    if (t < C_DIM) ci[t] = cb[i * C_DIM + t];
    __syncthreads();
    {
        const float4* row = (const float4*)(cb + t * C_DIM);
        float s = 0.f;
#pragma unroll
        for (int c4 = 0; c4 < 16; c4++) {
            float4 v = row[c4];
            s = fmaf(ci[4 * c4 + 0], v.x, s);
            s = fmaf(ci[4 * c4 + 1], v.y, s);
            s = fmaf(ci[4 * c4 + 2], v.z, s);
            s = fmaf(ci[4 * c4 + 3], v.w, s);
        }
        g_G[i * K_CB + t] = -s;                 // negated for packed-add subtract
        if (t == i) g_h[i] = -0.5f * s;         // negated half-norm
    }
    if (t < C_DIM) g_cbT[t * K_CB + i] = ci[t]; // transposed copy
    if (t == 0) {
        // csq exactly as XLA:CPU vectorized reduce (NEON width 4):
        // 4 strided lane accumulators, strict per-op rounding (mul+add,
        // no FMA), shuffle-halving horizontal sum: (L0+L2)+(L1+L3).
        float l0 = 0.f, l1 = 0.f, l2 = 0.f, l3 = 0.f;
        for (int j = 0; j < 16; j++) {
            float v0 = ci[4 * j + 0], v1 = ci[4 * j + 1];
            float v2 = ci[4 * j + 2], v3 = ci[4 * j + 3];
            l0 = __fadd_rn(l0, __fmul_rn(v0, v0));
            l1 = __fadd_rn(l1, __fmul_rn(v1, v1));
            l2 = __fadd_rn(l2, __fmul_rn(v2, v2));
            l3 = __fadd_rn(l3, __fmul_rn(v3, v3));
        }
        g_csq[i] = __fadd_rn(__fadd_rn(l0, l2), __fadd_rn(l1, l3));
    }
    if (i == 0 && t < NQ) g_loss[t] = 0.0;
}

// Orderable-float packing: larger float -> larger uint (monotone).
__device__ __forceinline__ unsigned ford(float f) {
    unsigned u = __float_as_uint(f);
    return (u & 0x80000000u) ? ~u : (u | 0x80000000u);
}
__device__ __forceinline__ float funord(unsigned s) {
    unsigned u = (s & 0x80000000u) ? (s ^ 0x80000000u) : ~s;
    return __uint_as_float(u);
}

// ---------------------------------------------------------------------------
// Main fused RVQ kernel. Block = 16 points x 512 codewords, 256 threads,
// 3 blocks/SM. Thread tile: 8 points (pg=tid&1) x 4 k's (kg=tid>>1) with
// k-pairs packed in f32x2 -> acc2[8][2] = 32 regs. Codebook streamed
// directly from L2 (g_cbT) -- the matmul has ZERO barriers.
// ---------------------------------------------------------------------------
__global__ __launch_bounds__(NTHR, 3)
void rvq_kernel(const float* __restrict__ x, const float* __restrict__ cb,
                float* __restrict__ out) {
    __shared__ ull rs2[C_DIM][P_BLK];           // residual, duplicated-packed (8KB)
    __shared__ unsigned red1[P_BLK];            // fast max per point
    __shared__ ull redmin[P_BLK];               // packed (dist,k) argmin
    __shared__ int    idxs[NQ][P_BLK];
    __shared__ double sloss[NQ];
    __shared__ int    wl[WLCAP];                // candidate worklist (p<<9|k)
    __shared__ int    wl_n;

    const int tid   = threadIdx.x;
    const int lane  = tid & 31;
    const int pg    = tid & 1;                  // 0..1, 8 points each
    const int kg    = tid >> 1;                 // 0..127
    const int kbase = kg * 4;
    const int n0    = blockIdx.x * P_BLK;
    const int b     = n0 / HW_SZ;               // 16 | HW, block never crosses b
    const int hw0   = n0 % HW_SZ;
    const float* xbase = x + (size_t)b * C_DIM * HW_SZ + hw0;

    if (tid < P_BLK) { red1[tid] = 0u; redmin[tid] = ~0ull; }
    if (tid < NQ)    sloss[tid] = 0.0;
    if (tid == 0)    wl_n = 0;

    const int p_e  = tid & 15;       // elementwise-phase point
    const int cg_e = tid >> 4;       // elementwise-phase channel group (0..15)

    // ---- load x tile; rs2 holds exact residual, duplicated in both halves ----
#pragma unroll
    for (int ii = 0; ii < 4; ii++) {
        const int c = cg_e * 4 + ii;
        float v = xbase[(size_t)c * HW_SZ + p_e];
        rs2[c][p_e] = pack2(v, v);
    }

    // ---- acc init: packed (-0.5||c_k||^2) pairs ----
    ull acc2[8][2];
    {
        ulonglong2 h2 = *((const ulonglong2*)(g_h + kbase));
#pragma unroll
        for (int i = 0; i < 8; i++) { acc2[i][0] = h2.x; acc2[i][1] = h2.y; }
    }
    __syncthreads();

    // ---- barrier-free matmul: acc += x[p] * cbT[c][k], packed over k ----
    {
        const float* cvp = g_cbT + kbase;
        const ull*   rsp = &rs2[0][pg * 8];
#pragma unroll 4
        for (int c = 0; c < C_DIM; c++) {
            ulonglong2 cv = *((const ulonglong2*)(cvp + (size_t)c * K_CB));
            ulonglong2 x0 = *((const ulonglong2*)(rsp + c * P_BLK + 0));
            ulonglong2 x1 = *((const ulonglong2*)(rsp + c * P_BLK + 2));
            ulonglong2 x2 = *((const ulonglong2*)(rsp + c * P_BLK + 4));
            ulonglong2 x3 = *((const ulonglong2*)(rsp + c * P_BLK + 6));
            acc2[0][0] = fma2(x0.x, cv.x, acc2[0][0]);
            acc2[0][1] = fma2(x0.x, cv.y, acc2[0][1]);
            acc2[1][0] = fma2(x0.y, cv.x, acc2[1][0]);
            acc2[1][1] = fma2(x0.y, cv.y, acc2[1][1]);
            acc2[2][0] = fma2(x1.x, cv.x, acc2[2][0]);
            acc2[2][1] = fma2(x1.x, cv.y, acc2[2][1]);
            acc2[3][0] = fma2(x1.y, cv.x, acc2[3][0]);
            acc2[3][1] = fma2(x1.y, cv.y, acc2[3][1]);
            acc2[4][0] = fma2(x2.x, cv.x, acc2[4][0]);
            acc2[4][1] = fma2(x2.x, cv.y, acc2[4][1]);
            acc2[5][0] = fma2(x2.y, cv.x, acc2[5][0]);
            acc2[5][1] = fma2(x2.y, cv.y, acc2[5][1]);
            acc2[6][0] = fma2(x3.x, cv.x, acc2[6][0]);
            acc2[6][1] = fma2(x3.x, cv.y, acc2[6][1]);
            acc2[7][0] = fma2(x3.y, cv.x, acc2[7][0]);
            acc2[7][1] = fma2(x3.y, cv.y, acc2[7][1]);
        }
    }
    __syncthreads();

    float qsum[4];                   // quantized accumulator (4 channels of p_e)
#pragma unroll
    for (int ii = 0; ii < 4; ii++) qsum[ii] = 0.f;

    // ---- 4 quantizer stages ----
#pragma unroll
    for (int q = 0; q < NQ; q++) {
        // A: fast local max per point; shfl pre-reduce over kg, then one
        //    smem atomic per (warp,point).
#pragma unroll
        for (int i = 0; i < 8; i++) {
            float a0, a1, a2, a3;
            unpack2(a0, a1, acc2[i][0]);
            unpack2(a2, a3, acc2[i][1]);
            float bv = fmaxf(fmaxf(a0, a1), fmaxf(a2, a3));
            bv = fmaxf(bv, __shfl_xor_sync(0xffffffffu, bv, 2));
            bv = fmaxf(bv, __shfl_xor_sync(0xffffffffu, bv, 4));
            bv = fmaxf(bv, __shfl_xor_sync(0xffffffffu, bv, 8));
            bv = fmaxf(bv, __shfl_xor_sync(0xffffffffu, bv, 16));
            if (lane < 2) atomicMax(&red1[pg * 8 + i], ford(bv));
        }
        __syncthreads();

        // B1: scan tile, push windowed candidates to worklist
#pragma unroll
        for (int i = 0; i < 8; i++) {
            const int p = pg * 8 + i;
            const float thr = funord(red1[p]) - 0.01f;
            float a[4];
            unpack2(a[0], a[1], acc2[i][0]);
            unpack2(a[2], a[3], acc2[i][1]);
#pragma unroll
            for (int j = 0; j < 4; j++) {
                if (a[j] >= thr) {
                    int pos = atomicAdd(&wl_n, 1);
                    if (pos < WLCAP) wl[pos] = (p << 9) | (kbase + j);
                }
            }
        }
        __syncthreads();

        // B2: exact (reference-order) dist per candidate, one thread each
        {
            const int wn = (wl_n < WLCAP) ? wl_n : WLCAP;
            for (int t = tid; t < wn; t += NTHR) {
                const int e = wl[t];
                const int p = e >> 9;
                const int k = e & 511;
                const float4* c4 = (const float4*)(cb + k * C_DIM);
                float dot = 0.f;
#pragma unroll 4
                for (int g = 0; g < 16; g++) {           // ascending-c seq FMA
                    float4 v = c4[g];                     // (Eigen gebp order)
                    dot = fmaf(*(const float*)&rs2[4*g+0][p], v.x, dot);
                    dot = fmaf(*(const float*)&rs2[4*g+1][p], v.y, dot);
                    dot = fmaf(*(const float*)&rs2[4*g+2][p], v.z, dot);
                    dot = fmaf(*(const float*)&rs2[4*g+3][p], v.w, dot);
                }
                float dist = __fsub_rn(g_csq[k], __fmul_rn(2.0f, dot));
                ull pk = ((ull)ford(dist) << 32) | (unsigned)k;
                atomicMin(&redmin[p], pk);               // min dist, then min k
            }
        }
        __syncthreads();

        // C: finalize pick, reset reducers + worklist
        if (tid < P_BLK) {
            idxs[q][tid] = (int)(unsigned)(redmin[tid] & 0xffffffffull);
            red1[tid]   = 0u;
            redmin[tid] = ~0ull;
        }
        if (tid == 0) wl_n = 0;
        __syncthreads();

        // D: exact elementwise update (replicates reference rounding chain)
        {
            const int k = idxs[q][p_e];
            const float* crow = cb + k * C_DIM + cg_e * 4;
            double ls = 0.0;
#pragma unroll
            for (int ii = 0; ii < 4; ii++) {
                const int c = cg_e * 4 + ii;
                const float cv = crow[ii];
                const float r  = *(const float*)&rs2[c][p_e];
                const float d  = __fsub_rn(cv, r);          // quant - residual
                const float qst = __fadd_rn(r, d);          // straight-through
                qsum[ii] = __fadd_rn(qsum[ii], qst);        // quant_out += qst
                const float nr = __fsub_rn(r, cv);          // residual -= quant
                rs2[c][p_e] = pack2(nr, nr);
                const float sq = __fmul_rn(d, d);
                ls += (double)sq;
            }
            // warp-reduce the double, single smem atomic per warp
#pragma unroll
            for (int o = 16; o; o >>= 1)
                ls += __shfl_xor_sync(0xffffffffu, ls, o);
            if (lane == 0) atomicAdd(&sloss[q], ls);
        }

        // E: fast-score cascade: acc += (-G[idx]) row slice, packed
        if (q < NQ - 1) {
#pragma unroll
            for (int i = 0; i < 8; i++) {
                const int row = idxs[q][pg * 8 + i];
                ulonglong2 gv = *((const ulonglong2*)(g_G + row * K_CB + kbase));
                acc2[i][0] = add2(acc2[i][0], gv.x);
                acc2[i][1] = add2(acc2[i][1], gv.y);
            }
        }
        __syncthreads();
    }

    // ---- outputs ----
    // indices as float, coalesced: 64 threads cover 16 points x 4 stages
    if (tid < P_BLK * NQ) {
        const int q = tid & 3, p = tid >> 2;
        out[IDX_OFF + (size_t)(n0 + p) * NQ + q] = (float)idxs[q][p];
    }
    // quantized in [B,C,H,W] layout (coalesced over p)
    {
        float* obase = out + (size_t)b * C_DIM * HW_SZ + hw0 + p_e;
#pragma unroll
        for (int ii = 0; ii < 4; ii++) {
            const int c = cg_e * 4 + ii;
            obase[(size_t)c * HW_SZ] = qsum[ii];
        }
    }
    // commit losses: 4 global atomics per block, last block writes output
    if (tid < NQ) atomicAdd(&g_loss[tid], sloss[tid]);
    __syncthreads();
    if (tid == 0) {
        __threadfence();
        unsigned t = atomicAdd(&g_done, 1u);
        if (t == (unsigned)(gridDim.x - 1)) {
            __threadfence();
            g_done = 0;                        // reset for next launch/replay
#pragma unroll
            for (int qq = 0; qq < NQ; qq++)
                out[LOSS_OFF + qq] =
                    (float)(g_loss[qq] * (1.0 / (131072.0 * 64.0)));
        }
    }
}

extern "C" void kernel_launch(void* const* d_in, const int* in_sizes, int n_in,
                              void* d_out, int out_size) {
    (void)in_sizes; (void)n_in; (void)out_size;
    const float* x  = (const float*)d_in[0];
    const float* cb = (const float*)d_in[1];
    float* out = (float*)d_out;

    prep_kernel<<<K_CB, 512>>>(cb);
    rvq_kernel<<<NBLK, NTHR>>>(x, cb, out);
}

// round 9
// speedup vs baseline: 1.2566x; 1.0004x over previous
#include <cuda_runtime.h>
#include <cstdint>

#define N_PTS   131072
#define C_DIM   64
#define K_CB    512
#define NQ      4
#define HW_SZ   16384
#define P_BLK   16
#define NTHR    256
#define NBLK    (N_PTS / P_BLK)
#define WLCAP   512
#define IDX_OFF 8388608
#define LOSS_OFF 8912896

typedef unsigned long long ull;

// Scratch (allocation-free rule: __device__ globals)
__device__ float    g_G[K_CB * K_CB];    // NEGATED Gram -cb@cb.T (fast path)
__device__ float    g_h[K_CB];           // NEGATED half-norms -0.5||c||^2
__device__ float    g_csq[K_CB];         // ||c||^2, XLA-CPU vectorized-reduce order
__device__ float    g_cbT[C_DIM * K_CB]; // transposed codebook [c][k]
__device__ double   g_loss[NQ];
__device__ unsigned g_done = 0;

// Packed fp32x2 ops (sm_10x). Per-lane rn rounding == scalar fmaf/fadd.
__device__ __forceinline__ ull fma2(ull a, ull b, ull c) {
    ull d;
    asm("fma.rn.f32x2 %0, %1, %2, %3;" : "=l"(d) : "l"(a), "l"(b), "l"(c));
    return d;
}
__device__ __forceinline__ ull add2(ull a, ull b) {
    ull d;
    asm("add.rn.f32x2 %0, %1, %2;" : "=l"(d) : "l"(a), "l"(b));
    return d;
}
__device__ __forceinline__ ull pack2(float lo, float hi) {
    ull d;
    asm("mov.b64 %0, {%1, %2};" : "=l"(d) : "f"(lo), "f"(hi));
    return d;
}
__device__ __forceinline__ void unpack2(float& lo, float& hi, ull v) {
    asm("mov.b64 {%0, %1}, %2;" : "=f"(lo), "=f"(hi) : "l"(v));
}

// ---------------------------------------------------------------------------
// Precompute (negated) G, (negated) h, csq, cbT; zero loss accumulators.
// ---------------------------------------------------------------------------
__global__ void prep_kernel(const float* __restrict__ cb) {
    __shared__ float ci[C_DIM];
    const int i = blockIdx.x;
    const int t = threadIdx.x;
    if (t < C_DIM) ci[t] = cb[i * C_DIM + t];
    __syncthreads();
    {
        const float4* row = (const float4*)(cb + t * C_DIM);
        float s = 0.f;
#pragma unroll
        for (int c4 = 0; c4 < 16; c4++) {
            float4 v = row[c4];
            s = fmaf(ci[4 * c4 + 0], v.x, s);
            s = fmaf(ci[4 * c4 + 1], v.y, s);
            s = fmaf(ci[4 * c4 + 2], v.z, s);
            s = fmaf(ci[4 * c4 + 3], v.w, s);
        }
        g_G[i * K_CB + t] = -s;                 // negated for packed-add subtract
        if (t == i) g_h[i] = -0.5f * s;         // negated half-norm
    }
    if (t < C_DIM) g_cbT[t * K_CB + i] = ci[t]; // transposed copy
    if (t == 0) {
        // csq exactly as XLA:CPU vectorized reduce (NEON width 4):
        // 4 strided lane accumulators, strict per-op rounding (mul+add,
        // no FMA), shuffle-halving horizontal sum: (L0+L2)+(L1+L3).
        float l0 = 0.f, l1 = 0.f, l2 = 0.f, l3 = 0.f;
        for (int j = 0; j < 16; j++) {
            float v0 = ci[4 * j + 0], v1 = ci[4 * j + 1];
            float v2 = ci[4 * j + 2], v3 = ci[4 * j + 3];
            l0 = __fadd_rn(l0, __fmul_rn(v0, v0));
            l1 = __fadd_rn(l1, __fmul_rn(v1, v1));
            l2 = __fadd_rn(l2, __fmul_rn(v2, v2));
            l3 = __fadd_rn(l3, __fmul_rn(v3, v3));
        }
        g_csq[i] = __fadd_rn(__fadd_rn(l0, l2), __fadd_rn(l1, l3));
    }
    if (i == 0 && t < NQ) g_loss[t] = 0.0;
}

// Orderable-float packing: larger float -> larger uint (monotone).
__device__ __forceinline__ unsigned ford(float f) {
    unsigned u = __float_as_uint(f);
    return (u & 0x80000000u) ? ~u : (u | 0x80000000u);
}
__device__ __forceinline__ float funord(unsigned s) {
    unsigned u = (s & 0x80000000u) ? (s ^ 0x80000000u) : ~s;
    return __uint_as_float(u);
}

// ---------------------------------------------------------------------------
// Main fused RVQ kernel. Block = 16 points x 512 codewords, 256 threads,
// 3 blocks/SM. Thread tile: 8 points (pg=tid&1) x 4 k's (kg=tid>>1) with
// k-pairs packed in f32x2 -> acc2[8][2] = 32 regs. Codebook streamed
// directly from L2 (g_cbT) -- the matmul has ZERO barriers.
// ---------------------------------------------------------------------------
__global__ __launch_bounds__(NTHR, 3)
void rvq_kernel(const float* __restrict__ x, const float* __restrict__ cb,
                float* __restrict__ out) {
    __shared__ ull rs2[C_DIM][P_BLK];           // residual, duplicated-packed (8KB)
    __shared__ unsigned red1[P_BLK];            // fast max per point
    __shared__ ull redmin[P_BLK];               // packed (dist,k) argmin
    __shared__ int    idxs[NQ][P_BLK];
    __shared__ double sloss[NQ];
    __shared__ int    wl[WLCAP];                // candidate worklist (p<<9|k)
    __shared__ int    wl_n;

    const int tid   = threadIdx.x;
    const int lane  = tid & 31;
    const int pg    = tid & 1;                  // 0..1, 8 points each
    const int kg    = tid >> 1;                 // 0..127
    const int kbase = kg * 4;
    const int n0    = blockIdx.x * P_BLK;
    const int b     = n0 / HW_SZ;               // 16 | HW, block never crosses b
    const int hw0   = n0 % HW_SZ;
    const float* xbase = x + (size_t)b * C_DIM * HW_SZ + hw0;

    if (tid < P_BLK) { red1[tid] = 0u; redmin[tid] = ~0ull; }
    if (tid < NQ)    sloss[tid] = 0.0;
    if (tid == 0)    wl_n = 0;

    const int p_e  = tid & 15;       // elementwise-phase point
    const int cg_e = tid >> 4;       // elementwise-phase channel group (0..15)

    // ---- load x tile; rs2 holds exact residual, duplicated in both halves ----
#pragma unroll
    for (int ii = 0; ii < 4; ii++) {
        const int c = cg_e * 4 + ii;
        float v = xbase[(size_t)c * HW_SZ + p_e];
        rs2[c][p_e] = pack2(v, v);
    }

    // ---- acc init: packed (-0.5||c_k||^2) pairs ----
    ull acc2[8][2];
    {
        ulonglong2 h2 = *((const ulonglong2*)(g_h + kbase));
#pragma unroll
        for (int i = 0; i < 8; i++) { acc2[i][0] = h2.x; acc2[i][1] = h2.y; }
    }
    __syncthreads();

    // ---- barrier-free matmul: acc += x[p] * cbT[c][k], packed over k ----
    {
        const float* cvp = g_cbT + kbase;
        const ull*   rsp = &rs2[0][pg * 8];
#pragma unroll 4
        for (int c = 0; c < C_DIM; c++) {
            ulonglong2 cv = *((const ulonglong2*)(cvp + (size_t)c * K_CB));
            ulonglong2 x0 = *((const ulonglong2*)(rsp + c * P_BLK + 0));
            ulonglong2 x1 = *((const ulonglong2*)(rsp + c * P_BLK + 2));
            ulonglong2 x2 = *((const ulonglong2*)(rsp + c * P_BLK + 4));
            ulonglong2 x3 = *((const ulonglong2*)(rsp + c * P_BLK + 6));
            acc2[0][0] = fma2(x0.x, cv.x, acc2[0][0]);
            acc2[0][1] = fma2(x0.x, cv.y, acc2[0][1]);
            acc2[1][0] = fma2(x0.y, cv.x, acc2[1][0]);
            acc2[1][1] = fma2(x0.y, cv.y, acc2[1][1]);
            acc2[2][0] = fma2(x1.x, cv.x, acc2[2][0]);
            acc2[2][1] = fma2(x1.x, cv.y, acc2[2][1]);
            acc2[3][0] = fma2(x1.y, cv.x, acc2[3][0]);
            acc2[3][1] = fma2(x1.y, cv.y, acc2[3][1]);
            acc2[4][0] = fma2(x2.x, cv.x, acc2[4][0]);
            acc2[4][1] = fma2(x2.x, cv.y, acc2[4][1]);
            acc2[5][0] = fma2(x2.y, cv.x, acc2[5][0]);
            acc2[5][1] = fma2(x2.y, cv.y, acc2[5][1]);
            acc2[6][0] = fma2(x3.x, cv.x, acc2[6][0]);
            acc2[6][1] = fma2(x3.x, cv.y, acc2[6][1]);
            acc2[7][0] = fma2(x3.y, cv.x, acc2[7][0]);
            acc2[7][1] = fma2(x3.y, cv.y, acc2[7][1]);
        }
    }
    __syncthreads();

    float qsum[4];                   // quantized accumulator (4 channels of p_e)
#pragma unroll
    for (int ii = 0; ii < 4; ii++) qsum[ii] = 0.f;

    // ---- 4 quantizer stages ----
#pragma unroll
    for (int q = 0; q < NQ; q++) {
        // A: fast local max per point; shfl pre-reduce over kg, then one
        //    smem atomic per (warp,point).
#pragma unroll
        for (int i = 0; i < 8; i++) {
            float a0, a1, a2, a3;
            unpack2(a0, a1, acc2[i][0]);
            unpack2(a2, a3, acc2[i][1]);
            float bv = fmaxf(fmaxf(a0, a1), fmaxf(a2, a3));
            bv = fmaxf(bv, __shfl_xor_sync(0xffffffffu, bv, 2));
            bv = fmaxf(bv, __shfl_xor_sync(0xffffffffu, bv, 4));
            bv = fmaxf(bv, __shfl_xor_sync(0xffffffffu, bv, 8));
            bv = fmaxf(bv, __shfl_xor_sync(0xffffffffu, bv, 16));
            if (lane < 2) atomicMax(&red1[pg * 8 + i], ford(bv));
        }
        __syncthreads();

        // B1: scan tile, push windowed candidates to worklist
#pragma unroll
        for (int i = 0; i < 8; i++) {
            const int p = pg * 8 + i;
            const float thr = funord(red1[p]) - 0.01f;
            float a[4];
            unpack2(a[0], a[1], acc2[i][0]);
            unpack2(a[2], a[3], acc2[i][1]);
#pragma unroll
            for (int j = 0; j < 4; j++) {
                if (a[j] >= thr) {
                    int pos = atomicAdd(&wl_n, 1);
                    if (pos < WLCAP) wl[pos] = (p << 9) | (kbase + j);
                }
            }
        }
        __syncthreads();

        // B2: exact (reference-order) dist per candidate, one thread each
        {
            const int wn = (wl_n < WLCAP) ? wl_n : WLCAP;
            for (int t = tid; t < wn; t += NTHR) {
                const int e = wl[t];
                const int p = e >> 9;
                const int k = e & 511;
                const float4* c4 = (const float4*)(cb + k * C_DIM);
                float dot = 0.f;
#pragma unroll 4
                for (int g = 0; g < 16; g++) {           // ascending-c seq FMA
                    float4 v = c4[g];                     // (Eigen gebp order)
                    dot = fmaf(*(const float*)&rs2[4*g+0][p], v.x, dot);
                    dot = fmaf(*(const float*)&rs2[4*g+1][p], v.y, dot);
                    dot = fmaf(*(const float*)&rs2[4*g+2][p], v.z, dot);
                    dot = fmaf(*(const float*)&rs2[4*g+3][p], v.w, dot);
                }
                float dist = __fsub_rn(g_csq[k], __fmul_rn(2.0f, dot));
                ull pk = ((ull)ford(dist) << 32) | (unsigned)k;
                atomicMin(&redmin[p], pk);               // min dist, then min k
            }
        }
        __syncthreads();

        // C: finalize pick, reset reducers + worklist
        if (tid < P_BLK) {
            idxs[q][tid] = (int)(unsigned)(redmin[tid] & 0xffffffffull);
            red1[tid]   = 0u;
            redmin[tid] = ~0ull;
        }
        if (tid == 0) wl_n = 0;
        __syncthreads();

        // D: exact elementwise update (replicates reference rounding chain)
        {
            const int k = idxs[q][p_e];
            const float* crow = cb + k * C_DIM + cg_e * 4;
            double ls = 0.0;
#pragma unroll
            for (int ii = 0; ii < 4; ii++) {
                const int c = cg_e * 4 + ii;
                const float cv = crow[ii];
                const float r  = *(const float*)&rs2[c][p_e];
                const float d  = __fsub_rn(cv, r);          // quant - residual
                const float qst = __fadd_rn(r, d);          // straight-through
                qsum[ii] = __fadd_rn(qsum[ii], qst);        // quant_out += qst
                const float nr = __fsub_rn(r, cv);          // residual -= quant
                rs2[c][p_e] = pack2(nr, nr);
                const float sq = __fmul_rn(d, d);
                ls += (double)sq;
            }
            // warp-reduce the double, single smem atomic per warp
#pragma unroll
            for (int o = 16; o; o >>= 1)
                ls += __shfl_xor_sync(0xffffffffu, ls, o);
            if (lane == 0) atomicAdd(&sloss[q], ls);
        }

        // E: fast-score cascade: acc += (-G[idx]) row slice, packed
        if (q < NQ - 1) {
#pragma unroll
            for (int i = 0; i < 8; i++) {
                const int row = idxs[q][pg * 8 + i];
                ulonglong2 gv = *((const ulonglong2*)(g_G + row * K_CB + kbase));
                acc2[i][0] = add2(acc2[i][0], gv.x);
                acc2[i][1] = add2(acc2[i][1], gv.y);
            }
        }
        __syncthreads();
    }

    // ---- outputs ----
    // indices as float, coalesced: 64 threads cover 16 points x 4 stages
    if (tid < P_BLK * NQ) {
        const int q = tid & 3, p = tid >> 2;
        out[IDX_OFF + (size_t)(n0 + p) * NQ + q] = (float)idxs[q][p];
    }
    // quantized in [B,C,H,W] layout (coalesced over p)
    {
        float* obase = out + (size_t)b * C_DIM * HW_SZ + hw0 + p_e;
#pragma unroll
        for (int ii = 0; ii < 4; ii++) {
            const int c = cg_e * 4 + ii;
            obase[(size_t)c * HW_SZ] = qsum[ii];
        }
    }
    // commit losses: 4 global atomics per block, last block writes output
    if (tid < NQ) atomicAdd(&g_loss[tid], sloss[tid]);
    __syncthreads();
    if (tid == 0) {
        __threadfence();
        unsigned t = atomicAdd(&g_done, 1u);
        if (t == (unsigned)(gridDim.x - 1)) {
            __threadfence();
            g_done = 0;                        // reset for next launch/replay
#pragma unroll
            for (int qq = 0; qq < NQ; qq++)
                out[LOSS_OFF + qq] =
                    (float)(g_loss[qq] * (1.0 / (131072.0 * 64.0)));
        }
    }
}

extern "C" void kernel_launch(void* const* d_in, const int* in_sizes, int n_in,
                              void* d_out, int out_size) {
    (void)in_sizes; (void)n_in; (void)out_size;
    const float* x  = (const float*)d_in[0];
    const float* cb = (const float*)d_in[1];
    float* out = (float*)d_out;

    prep_kernel<<<K_CB, 512>>>(cb);
    rvq_kernel<<<NBLK, NTHR>>>(x, cb, out);
}

// round 11
// speedup vs baseline: 1.4532x; 1.1565x over previous
#include <cuda_runtime.h>
#include <cstdint>

#define N_PTS   131072
#define C_DIM   64
#define K_CB    512
#define NQ      4
#define HW_SZ   16384
#define P_BLK   16
#define NTHR    256
#define NBLK    (N_PTS / P_BLK)
#define WLCAP   512
#define IDX_OFF 8388608
#define LOSS_OFF 8912896

typedef unsigned long long ull;

// Scratch (allocation-free rule: __device__ globals)
__device__ float    g_G[K_CB * K_CB];    // NEGATED Gram -cb@cb.T (fast path)
__device__ float    g_h[K_CB];           // NEGATED half-norms -0.5||c||^2
__device__ float    g_csq[K_CB];         // ||c||^2, XLA-CPU vectorized-reduce order
__device__ float    g_cbT[C_DIM * K_CB]; // transposed codebook [c][k]
__device__ double   g_loss[NQ];
__device__ unsigned g_done = 0;

// Packed fp32x2 ops (sm_10x). Per-lane rn rounding == scalar fmaf/fadd.
__device__ __forceinline__ ull fma2(ull a, ull b, ull c) {
    ull d;
    asm("fma.rn.f32x2 %0, %1, %2, %3;" : "=l"(d) : "l"(a), "l"(b), "l"(c));
    return d;
}
__device__ __forceinline__ ull add2(ull a, ull b) {
    ull d;
    asm("add.rn.f32x2 %0, %1, %2;" : "=l"(d) : "l"(a), "l"(b));
    return d;
}
__device__ __forceinline__ ull pack2(float lo, float hi) {
    ull d;
    asm("mov.b64 %0, {%1, %2};" : "=l"(d) : "f"(lo), "f"(hi));
    return d;
}
__device__ __forceinline__ void unpack2(float& lo, float& hi, ull v) {
    asm("mov.b64 {%0, %1}, %2;" : "=f"(lo), "=f"(hi) : "l"(v));
}

// ---------------------------------------------------------------------------
// Precompute (negated) G, (negated) h, csq, cbT; zero loss accumulators.
// ---------------------------------------------------------------------------
__global__ void prep_kernel(const float* __restrict__ cb) {
    __shared__ float ci[C_DIM];
    const int i = blockIdx.x;
    const int t = threadIdx.x;
    if (t < C_DIM) ci[t] = cb[i * C_DIM + t];
    __syncthreads();
    {
        const float4* row = (const float4*)(cb + t * C_DIM);
        float s = 0.f;
#pragma unroll
        for (int c4 = 0; c4 < 16; c4++) {
            float4 v = row[c4];
            s = fmaf(ci[4 * c4 + 0], v.x, s);
            s = fmaf(ci[4 * c4 + 1], v.y, s);
            s = fmaf(ci[4 * c4 + 2], v.z, s);
            s = fmaf(ci[4 * c4 + 3], v.w, s);
        }
        g_G[i * K_CB + t] = -s;                 // negated for packed-add subtract
        if (t == i) g_h[i] = -0.5f * s;         // negated half-norm
    }
    if (t < C_DIM) g_cbT[t * K_CB + i] = ci[t]; // transposed copy
    if (t == 0) {
        // csq exactly as XLA:CPU vectorized reduce (NEON width 4):
        // 4 strided lane accumulators, strict per-op rounding (mul+add,
        // no FMA), shuffle-halving horizontal sum: (L0+L2)+(L1+L3).
        float l0 = 0.f, l1 = 0.f, l2 = 0.f, l3 = 0.f;
        for (int j = 0; j < 16; j++) {
            float v0 = ci[4 * j + 0], v1 = ci[4 * j + 1];
            float v2 = ci[4 * j + 2], v3 = ci[4 * j + 3];
            l0 = __fadd_rn(l0, __fmul_rn(v0, v0));
            l1 = __fadd_rn(l1, __fmul_rn(v1, v1));
            l2 = __fadd_rn(l2, __fmul_rn(v2, v2));
            l3 = __fadd_rn(l3, __fmul_rn(v3, v3));
        }
        g_csq[i] = __fadd_rn(__fadd_rn(l0, l2), __fadd_rn(l1, l3));
    }
    if (i == 0 && t < NQ) g_loss[t] = 0.0;
}

// Orderable-float packing: larger float -> larger uint (monotone).
__device__ __forceinline__ unsigned ford(float f) {
    unsigned u = __float_as_uint(f);
    return (u & 0x80000000u) ? ~u : (u | 0x80000000u);
}
__device__ __forceinline__ float funord(unsigned s) {
    unsigned u = (s & 0x80000000u) ? (s ^ 0x80000000u) : ~s;
    return __uint_as_float(u);
}

// ---------------------------------------------------------------------------
// Main fused RVQ kernel. Block = 16 points x 512 codewords, 256 threads,
// 4 blocks/SM. Thread tile: 8 points (pg=tid&1) x 4 k's (kg=tid>>1), with
// POINT-pairs packed in f32x2 -> acc2[4][4] = 32 regs. Residuals stored as
// plain fp32 (adjacent points load as naturally packed pairs). Codebook
// streamed from L2 (g_cbT); the matmul has ZERO barriers.
// ---------------------------------------------------------------------------
__global__ __launch_bounds__(NTHR, 4)
void rvq_kernel(const float* __restrict__ x, const float* __restrict__ cb,
                float* __restrict__ out) {
    __shared__ float rs[C_DIM][P_BLK];          // exact residual, plain fp32 (4KB)
    __shared__ unsigned red1[P_BLK];            // fast max per point
    __shared__ ull redmin[P_BLK];               // packed (dist,k) argmin
    __shared__ int    idxs[NQ][P_BLK];
    __shared__ double sloss[NQ];
    __shared__ int    wl[WLCAP];                // candidate worklist (p<<9|k)
    __shared__ int    wl_n;

    const int tid   = threadIdx.x;
    const int lane  = tid & 31;
    const int pg    = tid & 1;                  // 0..1, 8 points each
    const int kg    = tid >> 1;                 // 0..127
    const int kbase = kg * 4;
    const int n0    = blockIdx.x * P_BLK;
    const int b     = n0 / HW_SZ;               // 16 | HW, block never crosses b
    const int hw0   = n0 % HW_SZ;
    const float* xbase = x + (size_t)b * C_DIM * HW_SZ + hw0;

    if (tid < P_BLK) { red1[tid] = 0u; redmin[tid] = ~0ull; }
    if (tid < NQ)    sloss[tid] = 0.0;
    if (tid == 0)    wl_n = 0;

    const int p_e  = tid & 15;       // elementwise-phase point
    const int cg_e = tid >> 4;       // elementwise-phase channel group (0..15)

    // ---- load x tile (coalesced over p); rs starts as x (exact residual) ----
#pragma unroll
    for (int ii = 0; ii < 4; ii++) {
        const int c = cg_e * 4 + ii;
        rs[c][p_e] = xbase[(size_t)c * HW_SZ + p_e];
    }

    // ---- acc init: packed (-0.5||c_k||^2), same value both point-halves ----
    ull acc2[4][4];
    {
        float4 hv = *((const float4*)(g_h + kbase));
        ull h0 = pack2(hv.x, hv.x), h1 = pack2(hv.y, hv.y);
        ull h2 = pack2(hv.z, hv.z), h3 = pack2(hv.w, hv.w);
#pragma unroll
        for (int i = 0; i < 4; i++) {
            acc2[i][0] = h0; acc2[i][1] = h1;
            acc2[i][2] = h2; acc2[i][3] = h3;
        }
    }
    __syncthreads();

    // ---- barrier-free matmul: acc += x[pair] * cbT[c][k] ----
    // Per (p,k) cell: one fma.rn per ascending c — byte-identical chain to
    // the validated scalar/dup-packed versions.
    {
        const float4* cvp = (const float4*)(g_cbT + kbase);
#pragma unroll 4
        for (int c = 0; c < C_DIM; c++) {
            ulonglong2 xa = *((const ulonglong2*)&rs[c][pg * 8]);     // (p0,p1),(p2,p3)
            ulonglong2 xb = *((const ulonglong2*)&rs[c][pg * 8 + 4]); // (p4,p5),(p6,p7)
            float4 cv = __ldg(cvp + (size_t)c * (K_CB / 4));
            ull c0 = pack2(cv.x, cv.x), c1 = pack2(cv.y, cv.y);
            ull c2 = pack2(cv.z, cv.z), c3 = pack2(cv.w, cv.w);
            acc2[0][0] = fma2(xa.x, c0, acc2[0][0]);
            acc2[0][1] = fma2(xa.x, c1, acc2[0][1]);
            acc2[0][2] = fma2(xa.x, c2, acc2[0][2]);
            acc2[0][3] = fma2(xa.x, c3, acc2[0][3]);
            acc2[1][0] = fma2(xa.y, c0, acc2[1][0]);
            acc2[1][1] = fma2(xa.y, c1, acc2[1][1]);
            acc2[1][2] = fma2(xa.y, c2, acc2[1][2]);
            acc2[1][3] = fma2(xa.y, c3, acc2[1][3]);
            acc2[2][0] = fma2(xb.x, c0, acc2[2][0]);
            acc2[2][1] = fma2(xb.x, c1, acc2[2][1]);
            acc2[2][2] = fma2(xb.x, c2, acc2[2][2]);
            acc2[2][3] = fma2(xb.x, c3, acc2[2][3]);
            acc2[3][0] = fma2(xb.y, c0, acc2[3][0]);
            acc2[3][1] = fma2(xb.y, c1, acc2[3][1]);
            acc2[3][2] = fma2(xb.y, c2, acc2[3][2]);
            acc2[3][3] = fma2(xb.y, c3, acc2[3][3]);
        }
    }
    __syncthreads();

    float qsum[4];                   // quantized accumulator (4 channels of p_e)
#pragma unroll
    for (int ii = 0; ii < 4; ii++) qsum[ii] = 0.f;

    // ---- 4 quantizer stages ----
#pragma unroll
    for (int q = 0; q < NQ; q++) {
        // A: fast local max per point; shfl pre-reduce over kg (same-pg lanes
        //    differ in lane bits 1..4), then one smem atomic per (warp,point).
#pragma unroll
        for (int i = 0; i < 4; i++) {
            float l0, h0, l1, h1, l2, h2, l3, h3;
            unpack2(l0, h0, acc2[i][0]);
            unpack2(l1, h1, acc2[i][1]);
            unpack2(l2, h2, acc2[i][2]);
            unpack2(l3, h3, acc2[i][3]);
            float blo = fmaxf(fmaxf(l0, l1), fmaxf(l2, l3));
            float bhi = fmaxf(fmaxf(h0, h1), fmaxf(h2, h3));
            blo = fmaxf(blo, __shfl_xor_sync(0xffffffffu, blo, 2));
            blo = fmaxf(blo, __shfl_xor_sync(0xffffffffu, blo, 4));
            blo = fmaxf(blo, __shfl_xor_sync(0xffffffffu, blo, 8));
            blo = fmaxf(blo, __shfl_xor_sync(0xffffffffu, blo, 16));
            bhi = fmaxf(bhi, __shfl_xor_sync(0xffffffffu, bhi, 2));
            bhi = fmaxf(bhi, __shfl_xor_sync(0xffffffffu, bhi, 4));
            bhi = fmaxf(bhi, __shfl_xor_sync(0xffffffffu, bhi, 8));
            bhi = fmaxf(bhi, __shfl_xor_sync(0xffffffffu, bhi, 16));
            if (lane < 2) {
                atomicMax(&red1[pg * 8 + 2 * i + 0], ford(blo));
                atomicMax(&red1[pg * 8 + 2 * i + 1], ford(bhi));
            }
        }
        __syncthreads();

        // B1: scan tile, push windowed candidates to worklist
#pragma unroll
        for (int i = 0; i < 4; i++) {
            const int pLo = pg * 8 + 2 * i, pHi = pLo + 1;
            const float thrLo = funord(red1[pLo]) - 0.01f;
            const float thrHi = funord(red1[pHi]) - 0.01f;
            float alo[4], ahi[4];
            unpack2(alo[0], ahi[0], acc2[i][0]);
            unpack2(alo[1], ahi[1], acc2[i][1]);
            unpack2(alo[2], ahi[2], acc2[i][2]);
            unpack2(alo[3], ahi[3], acc2[i][3]);
#pragma unroll
            for (int j = 0; j < 4; j++) {
                if (alo[j] >= thrLo) {
                    int pos = atomicAdd(&wl_n, 1);
                    if (pos < WLCAP) wl[pos] = (pLo << 9) | (kbase + j);
                }
                if (ahi[j] >= thrHi) {
                    int pos = atomicAdd(&wl_n, 1);
                    if (pos < WLCAP) wl[pos] = (pHi << 9) | (kbase + j);
                }
            }
        }
        __syncthreads();

        // B2: exact (reference-order) dist per candidate, one thread each
        {
            const int wn = (wl_n < WLCAP) ? wl_n : WLCAP;
            for (int t = tid; t < wn; t += NTHR) {
                const int e = wl[t];
                const int p = e >> 9;
                const int k = e & 511;
                const float4* c4 = (const float4*)(cb + k * C_DIM);
                float dot = 0.f;
#pragma unroll 4
                for (int g = 0; g < 16; g++) {           // ascending-c seq FMA
                    float4 v = c4[g];                     // (Eigen gebp order)
                    dot = fmaf(rs[4 * g + 0][p], v.x, dot);
                    dot = fmaf(rs[4 * g + 1][p], v.y, dot);
                    dot = fmaf(rs[4 * g + 2][p], v.z, dot);
                    dot = fmaf(rs[4 * g + 3][p], v.w, dot);
                }
                float dist = __fsub_rn(g_csq[k], __fmul_rn(2.0f, dot));
                ull pk = ((ull)ford(dist) << 32) | (unsigned)k;
                atomicMin(&redmin[p], pk);               // min dist, then min k
            }
        }
        __syncthreads();

        // C: finalize pick, reset reducers + worklist
        if (tid < P_BLK) {
            idxs[q][tid] = (int)(unsigned)(redmin[tid] & 0xffffffffull);
            red1[tid]   = 0u;
            redmin[tid] = ~0ull;
        }
        if (tid == 0) wl_n = 0;
        __syncthreads();

        // D: exact elementwise update (replicates reference rounding chain)
        {
            const int k = idxs[q][p_e];
            const float* crow = cb + k * C_DIM + cg_e * 4;
            double ls = 0.0;
#pragma unroll
            for (int ii = 0; ii < 4; ii++) {
                const int c = cg_e * 4 + ii;
                const float cv = crow[ii];
                const float r  = rs[c][p_e];
                const float d  = __fsub_rn(cv, r);          // quant - residual
                const float qst = __fadd_rn(r, d);          // straight-through
                qsum[ii] = __fadd_rn(qsum[ii], qst);        // quant_out += qst
                rs[c][p_e] = __fsub_rn(r, cv);              // residual -= quant
                ls += (double)__fmul_rn(d, d);
            }
            // warp-reduce the double, single smem atomic per warp
#pragma unroll
            for (int o = 16; o; o >>= 1)
                ls += __shfl_xor_sync(0xffffffffu, ls, o);
            if (lane == 0) atomicAdd(&sloss[q], ls);
        }

        // E: fast-score cascade: acc += (-G[idx]) slices, point-pair packed
        if (q < NQ - 1) {
#pragma unroll
            for (int i = 0; i < 4; i++) {
                const int rowLo = idxs[q][pg * 8 + 2 * i + 0];
                const int rowHi = idxs[q][pg * 8 + 2 * i + 1];
                float4 gl = *((const float4*)(g_G + (size_t)rowLo * K_CB + kbase));
                float4 gh = *((const float4*)(g_G + (size_t)rowHi * K_CB + kbase));
                acc2[i][0] = add2(acc2[i][0], pack2(gl.x, gh.x));
                acc2[i][1] = add2(acc2[i][1], pack2(gl.y, gh.y));
                acc2[i][2] = add2(acc2[i][2], pack2(gl.z, gh.z));
                acc2[i][3] = add2(acc2[i][3], pack2(gl.w, gh.w));
            }
        }
        __syncthreads();
    }

    // ---- outputs ----
    // indices as float, coalesced: 64 threads cover 16 points x 4 stages
    if (tid < P_BLK * NQ) {
        const int q = tid & 3, p = tid >> 2;
        out[IDX_OFF + (size_t)(n0 + p) * NQ + q] = (float)idxs[q][p];
    }
    // quantized in [B,C,H,W] layout (coalesced over p)
    {
        float* obase = out + (size_t)b * C_DIM * HW_SZ + hw0 + p_e;
#pragma unroll
        for (int ii = 0; ii < 4; ii++) {
            const int c = cg_e * 4 + ii;
            obase[(size_t)c * HW_SZ] = qsum[ii];
        }
    }
    // commit losses: 4 global atomics per block, last block writes output
    if (tid < NQ) atomicAdd(&g_loss[tid], sloss[tid]);
    __syncthreads();
    if (tid == 0) {
        __threadfence();
        unsigned t = atomicAdd(&g_done, 1u);
        if (t == (unsigned)(gridDim.x - 1)) {
            __threadfence();
            g_done = 0;                        // reset for next launch/replay
#pragma unroll
            for (int qq = 0; qq < NQ; qq++)
                out[LOSS_OFF + qq] =
                    (float)(g_loss[qq] * (1.0 / (131072.0 * 64.0)));
        }
    }
}

extern "C" void kernel_launch(void* const* d_in, const int* in_sizes, int n_in,
                              void* d_out, int out_size) {
    (void)in_sizes; (void)n_in; (void)out_size;
    const float* x  = (const float*)d_in[0];
    const float* cb = (const float*)d_in[1];
    float* out = (float*)d_out;

    prep_kernel<<<K_CB, 512>>>(cb);
    rvq_kernel<<<NBLK, NTHR>>>(x, cb, out);
}